// round 10
// baseline (speedup 1.0000x reference)
#include <cuda_runtime.h>
#include <math.h>

#define IMGS  16
#define H     256
#define W     256
#define NPIX  (H * W)            // 65536
#define TOTAL (IMGS * NPIX)      // 1048576
#define BIG2  1.0e12f            // (1e6)^2 for "no opposite pixel in column"
#define BIGF  3.0e37f
#define GUARD 9.0f               // (RWIN+1)^2 exactness guard, RWIN=2
#define RPB   4                  // rows (= warps) per block in the row kernel
#define NROWBLK (IMGS * H / RPB) // 1024

// ---- scratch (static __device__ arrays; allocation-free per harness rules) ----
__device__ float  s_buf[TOTAL];    // signed squared vertical distance: +v^2 (fg) / -v^2 (bg)
__device__ float  d_maxabs[IMGS];
__device__ int    d_counts[IMGS];
__device__ double d_S[IMGS];
__device__ unsigned int d_done;    // completion counter for fused finalize

__device__ __forceinline__ float sqrt_approx(float x) {
    float r;
    asm("sqrt.approx.f32 %0, %1;" : "=f"(r) : "f"(x));
    return r;
}
__device__ __forceinline__ float tanh_approx(float x) {
    float r;
    asm("tanh.approx.f32 %0, %1;" : "=f"(r) : "f"(x));
    return r;
}

// ---------------------------------------------------------------------------
// Vertical EDT pass (validated). 128 blocks x 256 threads: each thread owns a
// 32-row segment of one column; bitmask loads (full MLP), clz/ffs segment
// summaries combined in shared, 32-step unrolled SEL chains. Output: signed v^2.
__global__ void col_pass_kernel(const float* __restrict__ target) {
    __shared__ int sHiF[8][32], sHiB[8][32];
    __shared__ int sLoF[8][32], sLoB[8][32];

    int blk   = blockIdx.x;
    int tid   = threadIdx.x;
    int b     = blk >> 3;
    int chunk = blk & 7;
    int t     = tid & 31;
    int w     = tid >> 5;
    int x     = chunk * 32 + t;
    int ybase = w * 32;

    const float* m = target + b * NPIX + x;
    unsigned word = 0;
    #pragma unroll
    for (int j = 0; j < 32; j++)
        if (m[(ybase + j) * W] > 0.5f) word |= (1u << j);
    int cnt = __popc(word);

    unsigned nw = ~word;
    sHiF[w][t] = word ? (ybase + 31 - __clz(word)) : -1000000;
    sHiB[w][t] = nw   ? (ybase + 31 - __clz(nw))   : -1000000;
    sLoF[w][t] = word ? (ybase + __ffs(word) - 1)  :  1000000;
    sLoB[w][t] = nw   ? (ybase + __ffs(nw) - 1)    :  1000000;
    __syncthreads();

    int lastf = -1000000, lastb = -1000000;
    for (int w2 = 0; w2 < w; w2++) {
        lastf = max(lastf, sHiF[w2][t]);
        lastb = max(lastb, sHiB[w2][t]);
    }
    int nextf = 1000000, nextb = 1000000;
    for (int w2 = w + 1; w2 < 8; w2++) {
        nextf = min(nextf, sLoF[w2][t]);
        nextb = min(nextb, sLoB[w2][t]);
    }

    unsigned pk[16];
    #pragma unroll
    for (int j = 0; j < 32; j++) {
        int  y  = ybase + j;
        bool fg = (word >> j) & 1;
        int  da = y - (fg ? lastb : lastf);
        if (da > 1000) da = 1000;
        if (j & 1) pk[j >> 1] |= ((unsigned)da << 16);
        else       pk[j >> 1]  =  (unsigned)da;
        if (fg) lastf = y; else lastb = y;
    }
    float* sbp = s_buf + b * NPIX + x;
    #pragma unroll
    for (int j = 31; j >= 0; j--) {
        int  y  = ybase + j;
        bool fg = (word >> j) & 1;
        int  db = (fg ? nextb : nextf) - y;
        if (fg) nextf = y; else nextb = y;
        int da = (int)((pk[j >> 1] >> ((j & 1) * 16)) & 0xffffu);
        int d  = min(da, db);
        float v2 = (d > 255) ? BIG2 : (float)(d * d);
        sbp[y * W] = fg ? v2 : -v2;
    }

    #pragma unroll
    for (int o = 16; o; o >>= 1) cnt += __shfl_xor_sync(0xffffffffu, cnt, o);
    if (t == 0) atomicAdd(&d_counts[b], cnt);
}

// ---------------------------------------------------------------------------
// Barrier-free row min-plus + sigmoid + reduction. One WARP per row, 8 px per
// thread; the +-2 halo comes from 4 register shuffles (lane-edge values
// replaced by replicated own-pixel values, which are dominated under
// max(sg*s+k^2, k^2) -> window stays exact; guard 9 with global-memory exact
// fallback). No smem tiles, no syncthreads on the main path. Per-block
// aggregation (4 warps) -> single fence + atomics; last block finalizes and
// resets replay state. 1024 blocks x 128 threads.
__global__ void row_fused_kernel(const float* __restrict__ pred, float* __restrict__ out) {
    int blk  = blockIdx.x;
    int b    = blk >> 6;                 // 64 blocks per image
    int tid  = threadIdx.x;
    int wp   = tid >> 5;                 // warp = row within block: 0..3
    int lane = tid & 31;
    int y    = (blk & 63) * RPB + wp;
    int base = b * NPIX + y * W;
    int x0   = lane * 8;

    __shared__ float wred[8];            // 4 warp maxes + 4 warp sums
    __shared__ int   is_last;

    // front-batched independent loads (MLP 4)
    const float4* sp = (const float4*)(s_buf + base + x0);
    const float4* pp = (const float4*)(pred  + base + x0);
    float4 sa = sp[0], sb = sp[1];
    float4 pa = pp[0], pb = pp[1];

    float a[12];                          // window values for x0-2 .. x0+9
    a[2] = sa.x; a[3] = sa.y; a[4]  = sa.z; a[5]  = sa.w;
    a[6] = sb.x; a[7] = sb.y; a[8]  = sb.z; a[9]  = sb.w;
    float hl2 = __shfl_up_sync(0xffffffffu, a[8], 1);    // left neighbor v[6]
    float hl1 = __shfl_up_sync(0xffffffffu, a[9], 1);    // left neighbor v[7]
    float hr0 = __shfl_down_sync(0xffffffffu, a[2], 1);  // right neighbor v[0]
    float hr1 = __shfl_down_sync(0xffffffffu, a[3], 1);  // right neighbor v[1]
    if (lane == 0)  { hl2 = a[2]; hl1 = a[2]; }          // row edge: replicate (dominated)
    if (lane == 31) { hr0 = a[9]; hr1 = a[9]; }
    a[0] = hl2; a[1] = hl1; a[10] = hr0; a[11] = hr1;

    float pr[8] = {pa.x, pa.y, pa.z, pa.w, pb.x, pb.y, pb.z, pb.w};

    float term = 0.f, amax = 0.f;
    #pragma unroll
    for (int p = 0; p < 8; p++) {
        float s_own = a[p + 2];
        float sg    = (s_own > 0.f) ? 1.f : -1.f;       // +1 fg, -1 bg
        // candidates q = x-2..x+2, k^2 = 4,1,0,1,4
        float bmin = fmaxf(sg * s_own, 0.f);
        bmin = fminf(bmin, fmaxf(fmaf(sg, a[p + 1], 1.f), 1.f));
        bmin = fminf(bmin, fmaxf(fmaf(sg, a[p + 3], 1.f), 1.f));
        bmin = fminf(bmin, fmaxf(fmaf(sg, a[p],     4.f), 4.f));
        bmin = fminf(bmin, fmaxf(fmaf(sg, a[p + 4], 4.f), 4.f));
        if (bmin > GUARD) {                             // rare exact full-row fallback
            const float* row = s_buf + base;
            float xp = (float)(x0 + p);
            bmin = BIGF;
            #pragma unroll 1
            for (int q = 0; q < W; q++) {
                float dx = xp - (float)q;
                float kk = dx * dx;
                bmin = fminf(bmin, fmaxf(fmaf(sg, __ldg(row + q), kk), kk));
            }
        }
        float sd   = sqrt_approx(bmin);                 // bmin >= 1 always
        amax       = fmaxf(amax, sd);
        float prob = fmaf(0.5f, tanh_approx(0.5f * pr[p]), 0.5f);  // sigmoid
        float sds  = (s_own > 0.f) ? -sd : sd;          // signed distance
        term       = fmaf(prob, sds, term);
    }

    #pragma unroll
    for (int o = 16; o; o >>= 1) {
        amax = fmaxf(amax, __shfl_xor_sync(0xffffffffu, amax, o));
        term +=            __shfl_xor_sync(0xffffffffu, term, o);
    }
    if (lane == 0) { wred[wp] = amax; wred[4 + wp] = term; }
    __syncthreads();

    if (tid == 0) {
        float  mx = wred[0];
        double sm = (double)wred[4];
        #pragma unroll
        for (int i = 1; i < 4; i++) { mx = fmaxf(mx, wred[i]); sm += (double)wred[4 + i]; }
        atomicMax((int*)&d_maxabs[b], __float_as_int(mx));   // non-neg floats order as ints
        atomicAdd(&d_S[b], sm);
        __threadfence();
        unsigned int old = atomicAdd(&d_done, 1u);
        is_last = (old == (unsigned)(NROWBLK - 1)) ? 1 : 0;
    }
    __syncthreads();

    if (is_last) {
        __threadfence();
        double contrib = 0.0;
        if (tid < IMGS) {
            int    cc = __ldcg(&d_counts[tid]);
            float  mx = __ldcg(&d_maxabs[tid]);
            double S  = __ldcg(&d_S[tid]);
            if (cc > 0 && cc < NPIX)
                contrib = S / ((double)mx + 1e-6);
        }
        if (tid < 32) {
            #pragma unroll
            for (int o = 16; o; o >>= 1)
                contrib += __shfl_xor_sync(0xffffffffu, contrib, o);
            if (tid == 0) *out = (float)(contrib / (double)TOTAL);
        }
        // reset accumulators for the next graph replay
        if (tid < IMGS) { d_S[tid] = 0.0; d_maxabs[tid] = 0.0f; d_counts[tid] = 0; }
        if (tid == 0)   d_done = 0u;
    }
}

// ---------------------------------------------------------------------------
extern "C" void kernel_launch(void* const* d_in, const int* in_sizes, int n_in,
                              void* d_out, int out_size) {
    const float* pred   = (const float*)d_in[0];
    const float* target = (const float*)d_in[1];
    float* out = (float*)d_out;

    col_pass_kernel<<<IMGS * 8, 256>>>(target);
    row_fused_kernel<<<NROWBLK, 128>>>(pred, out);
}

// round 11
// speedup vs baseline: 1.2216x; 1.2216x over previous
#include <cuda_runtime.h>
#include <math.h>

#define IMGS  16
#define H     256
#define W     256
#define NPIX  (H * W)            // 65536
#define TOTAL (IMGS * NPIX)      // 1048576
#define BIG2  1.0e12f            // (1e6)^2 for "no opposite pixel in column"
#define BIGF  3.0e37f
#define GUARD 9.0f               // (RWIN+1)^2 exactness guard, RWIN=2
#define RPB   8                  // rows per block in the row kernel
#define RTHREADS 512             // row-kernel block size
#define NROWBLK (IMGS * H / RPB) // 512

// ---- scratch (static __device__ arrays; allocation-free per harness rules) ----
__device__ float  s_buf[TOTAL];    // signed squared vertical distance: +v^2 (fg) / -v^2 (bg)
__device__ float  d_maxabs[IMGS];
__device__ int    d_counts[IMGS];
__device__ double d_S[IMGS];
__device__ unsigned int d_done;    // completion counter for fused finalize

__device__ __forceinline__ float sqrt_approx(float x) {
    float r;
    asm("sqrt.approx.f32 %0, %1;" : "=f"(r) : "f"(x));
    return r;
}
__device__ __forceinline__ float tanh_approx(float x) {
    float r;
    asm("tanh.approx.f32 %0, %1;" : "=f"(r) : "f"(x));
    return r;
}

// ---------------------------------------------------------------------------
// Vertical EDT pass (validated, unchanged). 128 blocks x 256 threads.
__global__ void col_pass_kernel(const float* __restrict__ target) {
    __shared__ int sHiF[8][32], sHiB[8][32];
    __shared__ int sLoF[8][32], sLoB[8][32];

    int blk   = blockIdx.x;
    int tid   = threadIdx.x;
    int b     = blk >> 3;
    int chunk = blk & 7;
    int t     = tid & 31;
    int w     = tid >> 5;
    int x     = chunk * 32 + t;
    int ybase = w * 32;

    const float* m = target + b * NPIX + x;
    unsigned word = 0;
    #pragma unroll
    for (int j = 0; j < 32; j++)
        if (m[(ybase + j) * W] > 0.5f) word |= (1u << j);
    int cnt = __popc(word);

    unsigned nw = ~word;
    sHiF[w][t] = word ? (ybase + 31 - __clz(word)) : -1000000;
    sHiB[w][t] = nw   ? (ybase + 31 - __clz(nw))   : -1000000;
    sLoF[w][t] = word ? (ybase + __ffs(word) - 1)  :  1000000;
    sLoB[w][t] = nw   ? (ybase + __ffs(nw) - 1)    :  1000000;
    __syncthreads();

    int lastf = -1000000, lastb = -1000000;
    for (int w2 = 0; w2 < w; w2++) {
        lastf = max(lastf, sHiF[w2][t]);
        lastb = max(lastb, sHiB[w2][t]);
    }
    int nextf = 1000000, nextb = 1000000;
    for (int w2 = w + 1; w2 < 8; w2++) {
        nextf = min(nextf, sLoF[w2][t]);
        nextb = min(nextb, sLoB[w2][t]);
    }

    unsigned pk[16];
    #pragma unroll
    for (int j = 0; j < 32; j++) {
        int  y  = ybase + j;
        bool fg = (word >> j) & 1;
        int  da = y - (fg ? lastb : lastf);
        if (da > 1000) da = 1000;
        if (j & 1) pk[j >> 1] |= ((unsigned)da << 16);
        else       pk[j >> 1]  =  (unsigned)da;
        if (fg) lastf = y; else lastb = y;
    }
    float* sbp = s_buf + b * NPIX + x;
    #pragma unroll
    for (int j = 31; j >= 0; j--) {
        int  y  = ybase + j;
        bool fg = (word >> j) & 1;
        int  db = (fg ? nextb : nextf) - y;
        if (fg) nextf = y; else nextb = y;
        int da = (int)((pk[j >> 1] >> ((j & 1) * 16)) & 0xffffu);
        int d  = min(da, db);
        float v2 = (d > 255) ? BIG2 : (float)(d * d);
        sbp[y * W] = fg ? v2 : -v2;
    }

    #pragma unroll
    for (int o = 16; o; o >>= 1) cnt += __shfl_xor_sync(0xffffffffu, cnt, o);
    if (t == 0) atomicAdd(&d_counts[b], cnt);
}

// ---------------------------------------------------------------------------
// Fused row min-plus + sigmoid + per-image reduction + last-block finalize.
// 8 rows per block (512 threads), 4 pixels per thread -> 8192 warps total
// (validated latency-hiding point). Branch-free window math into registers;
// ONE warp-uniform deferred fallback region (P ~ 1e-5 per warp). Candidate:
// g_c[q] + k^2 = max(sg*s[q] + k^2, k^2); window |x-q|<=2, guard 9 exact.
__global__ void row_fused_kernel(const float* __restrict__ pred, float* __restrict__ out) {
    int blk  = blockIdx.x;
    int b    = blk >> 5;                 // 32 blocks per image (H/RPB)
    int y0   = (blk & 31) * RPB;
    int tid  = threadIdx.x;
    int r    = tid >> 6;                 // row within block: 0..7
    int c    = tid & 63;                 // pixel-quad within row
    int base = b * NPIX + (y0 + r) * W;
    int x0   = c * 4;

    __shared__ float sh[RPB][W + 8];     // signed s tiles, +4 halo each side
    __shared__ float wred[32];           // 16 warp maxes + 16 warp sums
    __shared__ int   is_last;

    float4 s4 = *(const float4*)(s_buf + base + x0);
    *(float4*)&sh[r][x0 + 4] = s4;
    if (c == 0)  { sh[r][0] = s4.x; sh[r][1] = s4.x; sh[r][2] = s4.x; sh[r][3] = s4.x; }
    if (c == 63) { sh[r][W+4] = s4.w; sh[r][W+5] = s4.w; sh[r][W+6] = s4.w; sh[r][W+7] = s4.w; }
    float4 p4 = *(const float4*)(pred + base + x0);
    __syncthreads();

    // v[i] = sh[r][x0 + i], i=0..11 covers logical offsets -4..+7 (need -2..+5)
    float v[12];
    #pragma unroll
    for (int i = 0; i < 3; i++) {
        float4 a = *(const float4*)&sh[r][x0 + 4 * i];
        v[4*i] = a.x; v[4*i+1] = a.y; v[4*i+2] = a.z; v[4*i+3] = a.w;
    }
    float pr[4] = {p4.x, p4.y, p4.z, p4.w};

    // branch-free window minima for all 4 pixels
    float bm[4], sg[4];
    #pragma unroll
    for (int p = 0; p < 4; p++) {
        float s_own = v[p + 4];
        float g     = (s_own > 0.f) ? 1.f : -1.f;
        float m0 = fmaxf(g * s_own, 0.f);                        // q = x
        float m1 = fmaxf(fmaf(g, v[p + 3], 1.f), 1.f);           // q = x-1
        float m2 = fmaxf(fmaf(g, v[p + 5], 1.f), 1.f);           // q = x+1
        float m3 = fmaxf(fmaf(g, v[p + 2], 4.f), 4.f);           // q = x-2
        float m4 = fmaxf(fmaf(g, v[p + 6], 4.f), 4.f);           // q = x+2
        bm[p] = fminf(fminf(m0, fminf(m1, m2)), fminf(m3, m4));
        sg[p] = g;
    }

    // single warp-uniform deferred exact fallback (essentially never taken)
    bool need = (bm[0] > GUARD) | (bm[1] > GUARD) | (bm[2] > GUARD) | (bm[3] > GUARD);
    if (__any_sync(0xffffffffu, need)) {
        #pragma unroll
        for (int p = 0; p < 4; p++) {
            if (bm[p] > GUARD) {
                float xp = (float)(x0 + p);
                float m  = BIGF;
                #pragma unroll 1
                for (int q = 0; q < W; q++) {
                    float dx = xp - (float)q;
                    float kk = dx * dx;
                    m = fminf(m, fmaxf(fmaf(sg[p], sh[r][q + 4], kk), kk));
                }
                bm[p] = m;
            }
        }
    }

    // two independent accumulator chains
    float t0 = 0.f, t1 = 0.f, a0 = 0.f, a1 = 0.f;
    #pragma unroll
    for (int p = 0; p < 4; p++) {
        float sd   = sqrt_approx(bm[p]);                  // bm >= 1 always
        float prob = fmaf(0.5f, tanh_approx(0.5f * pr[p]), 0.5f);
        float sds  = (sg[p] > 0.f) ? -sd : sd;
        if (p & 1) { a1 = fmaxf(a1, sd); t1 = fmaf(prob, sds, t1); }
        else       { a0 = fmaxf(a0, sd); t0 = fmaf(prob, sds, t0); }
    }
    float term = t0 + t1;
    float amax = fmaxf(a0, a1);

    #pragma unroll
    for (int o = 16; o; o >>= 1) {
        amax = fmaxf(amax, __shfl_xor_sync(0xffffffffu, amax, o));
        term +=            __shfl_xor_sync(0xffffffffu, term, o);
    }
    int lane = tid & 31, wp = tid >> 5;
    if (lane == 0) { wred[wp] = amax; wred[16 + wp] = term; }
    __syncthreads();

    if (tid == 0) {
        float  mx = wred[0];
        double sm = (double)wred[16];
        #pragma unroll
        for (int i = 1; i < 16; i++) { mx = fmaxf(mx, wred[i]); sm += (double)wred[16 + i]; }
        atomicMax((int*)&d_maxabs[b], __float_as_int(mx));   // non-neg floats order as ints
        atomicAdd(&d_S[b], sm);
        __threadfence();
        unsigned int old = atomicAdd(&d_done, 1u);
        is_last = (old == (unsigned)(NROWBLK - 1)) ? 1 : 0;
    }
    __syncthreads();

    if (is_last) {
        __threadfence();
        double contrib = 0.0;
        if (tid < IMGS) {
            int    cc = __ldcg(&d_counts[tid]);
            float  mx = __ldcg(&d_maxabs[tid]);
            double S  = __ldcg(&d_S[tid]);
            if (cc > 0 && cc < NPIX)
                contrib = S / ((double)mx + 1e-6);
        }
        if (tid < 32) {
            #pragma unroll
            for (int o = 16; o; o >>= 1)
                contrib += __shfl_xor_sync(0xffffffffu, contrib, o);
            if (tid == 0) *out = (float)(contrib / (double)TOTAL);
        }
        // reset accumulators for the next graph replay
        if (tid < IMGS) { d_S[tid] = 0.0; d_maxabs[tid] = 0.0f; d_counts[tid] = 0; }
        if (tid == 0)   d_done = 0u;
    }
}

// ---------------------------------------------------------------------------
extern "C" void kernel_launch(void* const* d_in, const int* in_sizes, int n_in,
                              void* d_out, int out_size) {
    const float* pred   = (const float*)d_in[0];
    const float* target = (const float*)d_in[1];
    float* out = (float*)d_out;

    col_pass_kernel<<<IMGS * 8, 256>>>(target);
    row_fused_kernel<<<NROWBLK, RTHREADS>>>(pred, out);
}

// round 12
// speedup vs baseline: 1.3595x; 1.1128x over previous
#include <cuda_runtime.h>
#include <math.h>

#define IMGS  16
#define H     256
#define W     256
#define NPIX  (H * W)            // 65536
#define TOTAL (IMGS * NPIX)      // 1048576
#define BIG2  1.0e12f            // (1e6)^2 for "no opposite pixel in column"
#define BIGF  3.0e37f
#define GUARD 9.0f               // (RWIN+1)^2 exactness guard, RWIN=2
#define RPB   4                  // rows per block in the row kernel
#define NROWBLK (IMGS * H / RPB) // 1024

// ---- scratch (static __device__ arrays; allocation-free per harness rules) ----
__device__ float  s_buf[TOTAL];    // signed squared vertical distance: +v^2 (fg) / -v^2 (bg)
__device__ float  d_maxabs[IMGS];
__device__ int    d_counts[IMGS];
__device__ double d_S[IMGS];
__device__ unsigned int d_done;    // completion counter for fused finalize

__device__ __forceinline__ float sqrt_approx(float x) {
    float r;
    asm("sqrt.approx.f32 %0, %1;" : "=f"(r) : "f"(x));
    return r;
}
__device__ __forceinline__ float tanh_approx(float x) {
    float r;
    asm("tanh.approx.f32 %0, %1;" : "=f"(r) : "f"(x));
    return r;
}

// ---------------------------------------------------------------------------
// Vertical EDT pass (validated). 128 blocks x 256 threads: each thread owns a
// 32-row segment of one column; bitmask loads (full MLP), clz/ffs segment
// summaries combined in shared, 32-step unrolled SEL chains. Ends with
// griddepcontrol.launch_dependents so the row kernel can dispatch early (PDL).
__global__ void col_pass_kernel(const float* __restrict__ target) {
    __shared__ int sHiF[8][32], sHiB[8][32];
    __shared__ int sLoF[8][32], sLoB[8][32];

    int blk   = blockIdx.x;
    int tid   = threadIdx.x;
    int b     = blk >> 3;
    int chunk = blk & 7;
    int t     = tid & 31;
    int w     = tid >> 5;
    int x     = chunk * 32 + t;
    int ybase = w * 32;

    const float* m = target + b * NPIX + x;
    unsigned word = 0;
    #pragma unroll
    for (int j = 0; j < 32; j++)
        if (m[(ybase + j) * W] > 0.5f) word |= (1u << j);
    int cnt = __popc(word);

    unsigned nw = ~word;
    sHiF[w][t] = word ? (ybase + 31 - __clz(word)) : -1000000;
    sHiB[w][t] = nw   ? (ybase + 31 - __clz(nw))   : -1000000;
    sLoF[w][t] = word ? (ybase + __ffs(word) - 1)  :  1000000;
    sLoB[w][t] = nw   ? (ybase + __ffs(nw) - 1)    :  1000000;
    __syncthreads();

    int lastf = -1000000, lastb = -1000000;
    for (int w2 = 0; w2 < w; w2++) {
        lastf = max(lastf, sHiF[w2][t]);
        lastb = max(lastb, sHiB[w2][t]);
    }
    int nextf = 1000000, nextb = 1000000;
    for (int w2 = w + 1; w2 < 8; w2++) {
        nextf = min(nextf, sLoF[w2][t]);
        nextb = min(nextb, sLoB[w2][t]);
    }

    unsigned pk[16];
    #pragma unroll
    for (int j = 0; j < 32; j++) {
        int  y  = ybase + j;
        bool fg = (word >> j) & 1;
        int  da = y - (fg ? lastb : lastf);
        if (da > 1000) da = 1000;
        if (j & 1) pk[j >> 1] |= ((unsigned)da << 16);
        else       pk[j >> 1]  =  (unsigned)da;
        if (fg) lastf = y; else lastb = y;
    }
    float* sbp = s_buf + b * NPIX + x;
    #pragma unroll
    for (int j = 31; j >= 0; j--) {
        int  y  = ybase + j;
        bool fg = (word >> j) & 1;
        int  db = (fg ? nextb : nextf) - y;
        if (fg) nextf = y; else nextb = y;
        int da = (int)((pk[j >> 1] >> ((j & 1) * 16)) & 0xffffu);
        int d  = min(da, db);
        float v2 = (d > 255) ? BIG2 : (float)(d * d);
        sbp[y * W] = fg ? v2 : -v2;
    }

    #pragma unroll
    for (int o = 16; o; o >>= 1) cnt += __shfl_xor_sync(0xffffffffu, cnt, o);
    if (t == 0) atomicAdd(&d_counts[b], cnt);

    // signal dependents: all s_buf stores above are visible to the row kernel
    asm volatile("griddepcontrol.launch_dependents;" ::: "memory");
}

// ---------------------------------------------------------------------------
// Fused row min-plus + sigmoid + per-image reduction + last-block finalize.
// R7 geometry: 1024 blocks x 256 threads (8192 warps), 4 rows/block, 4 px/
// thread. PDL: pred load + sigmoid run BEFORE griddepcontrol.wait, hiding the
// prologue under the col kernel's tail. Branch-free RWIN=2 window, candidate
// g_c[q] + k^2 = max(sg*s[q] + k^2, k^2), guard 9 with one warp-uniform exact
// fallback region (P ~ 1e-9/pixel).
__global__ void row_fused_kernel(const float* __restrict__ pred, float* __restrict__ out) {
    int blk  = blockIdx.x;
    int b    = blk >> 6;                 // 64 blocks per image
    int y0   = (blk & 63) * RPB;
    int tid  = threadIdx.x;
    int r    = tid >> 6;                 // row within block: 0..3
    int c    = tid & 63;                 // pixel-quad within row
    int base = b * NPIX + (y0 + r) * W;
    int x0   = c * 4;

    __shared__ float sh[RPB][W + 8];     // signed s tiles, +4 halo each side
    __shared__ float wred[16];           // 8 warp maxes + 8 warp sums
    __shared__ int   is_last;

    // ---- pre-dependency work: pred is a harness input, valid immediately ----
    float4 p4 = *(const float4*)(pred + base + x0);
    float prob[4];
    prob[0] = fmaf(0.5f, tanh_approx(0.5f * p4.x), 0.5f);
    prob[1] = fmaf(0.5f, tanh_approx(0.5f * p4.y), 0.5f);
    prob[2] = fmaf(0.5f, tanh_approx(0.5f * p4.z), 0.5f);
    prob[3] = fmaf(0.5f, tanh_approx(0.5f * p4.w), 0.5f);

    // ---- wait for col kernel's s_buf stores (no-op if launched without PDL) --
    asm volatile("griddepcontrol.wait;" ::: "memory");

    float4 s4 = *(const float4*)(s_buf + base + x0);
    *(float4*)&sh[r][x0 + 4] = s4;
    if (c == 0)  { sh[r][0] = s4.x; sh[r][1] = s4.x; sh[r][2] = s4.x; sh[r][3] = s4.x; }
    if (c == 63) { sh[r][W+4] = s4.w; sh[r][W+5] = s4.w; sh[r][W+6] = s4.w; sh[r][W+7] = s4.w; }
    __syncthreads();

    // v[i] = sh[r][x0 + i], i=0..11 covers logical offsets -4..+7 (need -2..+5)
    float v[12];
    #pragma unroll
    for (int i = 0; i < 3; i++) {
        float4 a = *(const float4*)&sh[r][x0 + 4 * i];
        v[4*i] = a.x; v[4*i+1] = a.y; v[4*i+2] = a.z; v[4*i+3] = a.w;
    }

    // branch-free window minima for all 4 pixels
    float bm[4], sg[4];
    #pragma unroll
    for (int p = 0; p < 4; p++) {
        float s_own = v[p + 4];
        float g     = (s_own > 0.f) ? 1.f : -1.f;
        float m0 = fmaxf(g * s_own, 0.f);                        // q = x
        float m1 = fmaxf(fmaf(g, v[p + 3], 1.f), 1.f);           // q = x-1
        float m2 = fmaxf(fmaf(g, v[p + 5], 1.f), 1.f);           // q = x+1
        float m3 = fmaxf(fmaf(g, v[p + 2], 4.f), 4.f);           // q = x-2
        float m4 = fmaxf(fmaf(g, v[p + 6], 4.f), 4.f);           // q = x+2
        bm[p] = fminf(fminf(m0, fminf(m1, m2)), fminf(m3, m4));
        sg[p] = g;
    }

    // single warp-uniform deferred exact fallback (essentially never taken)
    bool need = (bm[0] > GUARD) | (bm[1] > GUARD) | (bm[2] > GUARD) | (bm[3] > GUARD);
    if (__any_sync(0xffffffffu, need)) {
        #pragma unroll
        for (int p = 0; p < 4; p++) {
            if (bm[p] > GUARD) {
                float xp = (float)(x0 + p);
                float m  = BIGF;
                #pragma unroll 1
                for (int q = 0; q < W; q++) {
                    float dx = xp - (float)q;
                    float kk = dx * dx;
                    m = fminf(m, fmaxf(fmaf(sg[p], sh[r][q + 4], kk), kk));
                }
                bm[p] = m;
            }
        }
    }

    // two independent accumulator chains
    float t0 = 0.f, t1 = 0.f, a0 = 0.f, a1 = 0.f;
    #pragma unroll
    for (int p = 0; p < 4; p++) {
        float sd  = sqrt_approx(bm[p]);                  // bm >= 1 always
        float sds = (sg[p] > 0.f) ? -sd : sd;            // signed distance
        if (p & 1) { a1 = fmaxf(a1, sd); t1 = fmaf(prob[p], sds, t1); }
        else       { a0 = fmaxf(a0, sd); t0 = fmaf(prob[p], sds, t0); }
    }
    float term = t0 + t1;
    float amax = fmaxf(a0, a1);

    #pragma unroll
    for (int o = 16; o; o >>= 1) {
        amax = fmaxf(amax, __shfl_xor_sync(0xffffffffu, amax, o));
        term +=            __shfl_xor_sync(0xffffffffu, term, o);
    }
    int lane = tid & 31, wp = tid >> 5;
    if (lane == 0) { wred[wp] = amax; wred[8 + wp] = term; }
    __syncthreads();

    if (tid == 0) {
        float  mx = wred[0];
        double sm = (double)wred[8];
        #pragma unroll
        for (int i = 1; i < 8; i++) { mx = fmaxf(mx, wred[i]); sm += (double)wred[8 + i]; }
        atomicMax((int*)&d_maxabs[b], __float_as_int(mx));   // non-neg floats order as ints
        atomicAdd(&d_S[b], sm);
        __threadfence();
        unsigned int old = atomicAdd(&d_done, 1u);
        is_last = (old == (unsigned)(NROWBLK - 1)) ? 1 : 0;
    }
    __syncthreads();

    if (is_last) {
        __threadfence();
        double contrib = 0.0;
        if (tid < IMGS) {
            int    cc = __ldcg(&d_counts[tid]);
            float  mx = __ldcg(&d_maxabs[tid]);
            double S  = __ldcg(&d_S[tid]);
            if (cc > 0 && cc < NPIX)
                contrib = S / ((double)mx + 1e-6);
        }
        if (tid < 32) {
            #pragma unroll
            for (int o = 16; o; o >>= 1)
                contrib += __shfl_xor_sync(0xffffffffu, contrib, o);
            if (tid == 0) *out = (float)(contrib / (double)TOTAL);
        }
        // reset accumulators for the next graph replay
        if (tid < IMGS) { d_S[tid] = 0.0; d_maxabs[tid] = 0.0f; d_counts[tid] = 0; }
        if (tid == 0)   d_done = 0u;
    }
}

// ---------------------------------------------------------------------------
extern "C" void kernel_launch(void* const* d_in, const int* in_sizes, int n_in,
                              void* d_out, int out_size) {
    const float* pred   = (const float*)d_in[0];
    const float* target = (const float*)d_in[1];
    float* out = (float*)d_out;

    col_pass_kernel<<<IMGS * 8, 256>>>(target);

    // Programmatic dependent launch: row kernel dispatches while col runs;
    // its griddepcontrol.wait gates the s_buf reads.
    cudaLaunchConfig_t cfg = {};
    cfg.gridDim  = dim3(NROWBLK);
    cfg.blockDim = dim3(256);
    cfg.dynamicSmemBytes = 0;
    cfg.stream = 0;
    cudaLaunchAttribute attrs[1];
    attrs[0].id = cudaLaunchAttributeProgrammaticStreamSerialization;
    attrs[0].val.programmaticStreamSerializationAllowed = 1;
    cfg.attrs = attrs;
    cfg.numAttrs = 1;
    cudaError_t e = cudaLaunchKernelEx(&cfg, row_fused_kernel, pred, out);
    if (e != cudaSuccess) {
        // fallback: plain serialized launch (griddepcontrol.wait is a no-op)
        row_fused_kernel<<<NROWBLK, 256>>>(pred, out);
    }
}